// round 16
// baseline (speedup 1.0000x reference)
#include <cuda_runtime.h>
#include <cuda_fp16.h>
#include <math_constants.h>
#include <cstdint>

#define BB 4
#define SS 2048
#define EE 1024
#define HH 16
#define DD 64
#define MM (BB*SS)   // 8192

// ---------------------------------------------------------------------------
// Device-global scratch (allocation-free rule) — all fp16
// ---------------------------------------------------------------------------
__device__ __align__(16) __half g_x16[MM*EE];
__device__ __align__(16) __half g_w16[48*DD*EE];    // [z*64+d][e] == W_all^T
__device__ __align__(16) __half g_wo16[EE*EE];      // [n][k] (wo transposed)
__device__ __align__(16) __half g_q16[BB*HH*SS*DD]; // [bh][s][d], pre-scaled by 1/sqrt(D)*log2e
__device__ __align__(16) __half g_k16[BB*HH*SS*DD];
__device__ __align__(16) __half g_v16[BB*HH*SS*DD];
__device__ __align__(16) __half g_o16[MM*EE];       // [m][h*64+d]

// ---------------------------------------------------------------------------
// mma.sync / ldmatrix / cp.async helpers
// ---------------------------------------------------------------------------
__device__ __forceinline__ uint32_t smem_to_u32(const void* p) {
    uint32_t a;
    asm("{ .reg .u64 t; cvta.to.shared.u64 t, %1; cvt.u32.u64 %0, t; }"
        : "=r"(a) : "l"(p));
    return a;
}
__device__ __forceinline__ void cp16(uint32_t saddr, const void* gaddr) {
    asm volatile("cp.async.cg.shared.global [%0], [%1], 16;"
                 :: "r"(saddr), "l"(gaddr));
}
#define CP_COMMIT() asm volatile("cp.async.commit_group;" ::: "memory")
#define CP_WAIT1()  asm volatile("cp.async.wait_group 1;" ::: "memory")
#define CP_WAIT2()  asm volatile("cp.async.wait_group 2;" ::: "memory")
#define CP_WAIT3()  asm volatile("cp.async.wait_group 3;" ::: "memory")
#define CP_WAIT0()  asm volatile("cp.async.wait_group 0;" ::: "memory")

__device__ __forceinline__ void ldmx4(uint32_t* r, uint32_t addr) {
    asm volatile("ldmatrix.sync.aligned.m8n8.x4.shared.b16 {%0,%1,%2,%3}, [%4];"
        : "=r"(r[0]), "=r"(r[1]), "=r"(r[2]), "=r"(r[3]) : "r"(addr));
}
__device__ __forceinline__ void ldmx4t(uint32_t* r, uint32_t addr) {
    asm volatile("ldmatrix.sync.aligned.m8n8.x4.trans.shared.b16 {%0,%1,%2,%3}, [%4];"
        : "=r"(r[0]), "=r"(r[1]), "=r"(r[2]), "=r"(r[3]) : "r"(addr));
}
__device__ __forceinline__ void mmah(float* c, const uint32_t* a,
                                     uint32_t b0, uint32_t b1) {
    asm volatile("mma.sync.aligned.m16n8k16.row.col.f32.f16.f16.f32 "
        "{%0,%1,%2,%3}, {%4,%5,%6,%7}, {%8,%9}, {%0,%1,%2,%3};"
        : "+f"(c[0]), "+f"(c[1]), "+f"(c[2]), "+f"(c[3])
        : "r"(a[0]), "r"(a[1]), "r"(a[2]), "r"(a[3]), "r"(b0), "r"(b1));
}

#define SWZ128(off) ((off) ^ (((off) >> 3) & 0x70))   // 128B rows

__device__ __forceinline__ uint32_t pckh(__half a, __half b) {
    return ((uint32_t)__half_as_ushort(b) << 16) | (uint32_t)__half_as_ushort(a);
}
__device__ __forceinline__ uint32_t cvt_pair(float v0, float v1) {
    return pckh(__float2half_rn(v0), __float2half_rn(v1));
}
__device__ __forceinline__ uint32_t cvtpair_f2h(float v0, float v1) {
    uint32_t r;
    asm("cvt.rn.f16x2.f32 %0, %1, %2;" : "=r"(r) : "f"(v1), "f"(v0));
    return r;
}
__device__ __forceinline__ uint32_t h2exp2(uint32_t x) {
    uint32_t r;
    asm("ex2.approx.f16x2 %0, %1;" : "=r"(r) : "r"(x));
    return r;
}

// ---------------------------------------------------------------------------
// Merged prep kernel: fp32 -> fp16 for x, W_all (transposed), wo (transposed)
// ---------------------------------------------------------------------------
__global__ __launch_bounds__(256) void prep_kernel(
    const float* __restrict__ x,
    const float* __restrict__ wq, const float* __restrict__ wk,
    const float* __restrict__ wv, const float* __restrict__ wo)
{
    __shared__ float t[64][65];
    const int bid = blockIdx.x;
    const int tid = threadIdx.x;

    if (bid < 4096) {
        size_t i = ((size_t)bid * 256 + tid) * 8;
        float4 v0 = *(const float4*)(x + i);
        float4 v1 = *(const float4*)(x + i + 4);
        uint4 u;
        u.x = cvt_pair(v0.x, v0.y); u.y = cvt_pair(v0.z, v0.w);
        u.z = cvt_pair(v1.x, v1.y); u.w = cvt_pair(v1.z, v1.w);
        *(uint4*)(g_x16 + i) = u;
    } else if (bid < 4096 + 768) {
        const int tt = bid - 4096;
        const int e0 = (tt & 15) * 64;
        const int z = tt >> 4;
        const int which = z >> 4, h = z & 15;
        const float* W = (which == 0 ? wq : which == 1 ? wk : wv) + (size_t)h * EE * DD;
        #pragma unroll
        for (int q = 0; q < 4; q++) {
            int idx = q * 256 + tid;
            int r = idx >> 4, c = (idx & 15) * 4;
            float4 v = *(const float4*)(W + (size_t)(e0 + r) * DD + c);
            t[r][c] = v.x; t[r][c+1] = v.y; t[r][c+2] = v.z; t[r][c+3] = v.w;
        }
        __syncthreads();
        #pragma unroll
        for (int q = 0; q < 4; q++) {
            int idx = q * 256 + tid;
            int d = idx >> 4, e = (idx & 15) * 4;
            size_t o = ((size_t)z * DD + d) * EE + e0 + e;
            *(uint32_t*)(g_w16 + o)     = cvt_pair(t[e][d],   t[e+1][d]);
            *(uint32_t*)(g_w16 + o + 2) = cvt_pair(t[e+2][d], t[e+3][d]);
        }
    } else {
        const int tt = bid - (4096 + 768);
        const int k0 = (tt & 15) * 64;
        const int n0 = (tt >> 4) * 64;
        #pragma unroll
        for (int q = 0; q < 4; q++) {
            int idx = q * 256 + tid;
            int r = idx >> 4, c = (idx & 15) * 4;
            float4 v = *(const float4*)(wo + (size_t)(k0 + r) * EE + n0 + c);
            t[r][c] = v.x; t[r][c+1] = v.y; t[r][c+2] = v.z; t[r][c+3] = v.w;
        }
        __syncthreads();
        #pragma unroll
        for (int q = 0; q < 4; q++) {
            int idx = q * 256 + tid;
            int d = idx >> 4, e = (idx & 15) * 4;
            size_t o = (size_t)(n0 + d) * EE + k0 + e;
            *(uint32_t*)(g_wo16 + o)     = cvt_pair(t[e][d],   t[e+1][d]);
            *(uint32_t*)(g_wo16 + o + 2) = cvt_pair(t[e+2][d], t[e+3][d]);
        }
    }
}

// ---------------------------------------------------------------------------
// GEMM core 128x128, fp16 single-pass (for qkv). Static-stage mainloop.
// ---------------------------------------------------------------------------
#define STAGE_BYTES 32768
#define GEMM_SMEM   (3 * STAGE_BYTES)

__device__ __forceinline__ void load_stage(
    uint32_t sb, int s, int kt, int tid,
    const char* ag, const char* bg)
{
    const uint32_t st = sb + (uint32_t)s * STAGE_BYTES;
    const int c16 = (tid & 7) * 16;
    const size_t gk = (size_t)kt * 128 + (size_t)c16;
    #pragma unroll
    for (int p = 0; p < 4; ++p) {
        int row = p * 32 + (tid >> 3);
        uint32_t so = SWZ128((uint32_t)(row * 128 + c16));
        size_t g = (size_t)row * 2048 + gk;
        cp16(st + so,         ag + g);
        cp16(st + 16384 + so, bg + g);
    }
}

template <int S>
__device__ __forceinline__ void gemm128_step(
    uint32_t sb, int kt, int tid,
    const char* ag, const char* bg,
    const uint32_t offA[2], const uint32_t offB[4],
    float acc[2][8][4])
{
    CP_WAIT1();
    __syncthreads();
    if (kt + 2 < 16)
        load_stage(sb, (S + 2) % 3, kt + 2, tid, ag, bg);
    CP_COMMIT();

    const uint32_t base = sb + (uint32_t)(S * STAGE_BYTES);
    #pragma unroll
    for (int s16 = 0; s16 < 4; ++s16) {
        const uint32_t sx = (uint32_t)(s16 * 32);
        uint32_t a0[4], a1[4];
        ldmx4(a0, base + (offA[0] ^ sx));
        ldmx4(a1, base + (offA[1] ^ sx));
        uint32_t b[4][4];
        #pragma unroll
        for (int g = 0; g < 4; ++g)
            ldmx4(b[g], base + 16384 + (offB[g] ^ sx));
        uint32_t* aa[2] = {a0, a1};
        #pragma unroll
        for (int f = 0; f < 2; ++f)
            #pragma unroll
            for (int nf = 0; nf < 8; ++nf)
                mmah(acc[f][nf], aa[f],
                     b[nf >> 1][(nf & 1) * 2], b[nf >> 1][(nf & 1) * 2 + 1]);
    }
}

__device__ __forceinline__ void gemm_core_128x128_h(
    uint32_t sb, const char* ag, const char* bg, float acc[2][8][4])
{
    const int tid = threadIdx.x;
    const int warp = tid >> 5, lane = tid & 31;
    const int wm = (warp & 3) * 32;
    const int wn = (warp >> 2) * 64;

    uint32_t offA[2], offB[4];
    {
        const int rbA = (lane & 7) + ((lane >> 3) & 1) * 8;
        const int cA  = (lane >> 4) & 1;
        const int rbB = (lane & 7) + ((lane >> 4) & 1) * 8;
        const int cB  = (lane >> 3) & 1;
        #pragma unroll
        for (int f = 0; f < 2; ++f)
            offA[f] = SWZ128((uint32_t)((wm + f*16 + rbA) * 128 + cA * 16));
        #pragma unroll
        for (int g = 0; g < 4; ++g)
            offB[g] = SWZ128((uint32_t)((wn + g*16 + rbB) * 128 + cB * 16));
    }
    #pragma unroll
    for (int f = 0; f < 2; f++)
        #pragma unroll
        for (int nf = 0; nf < 8; nf++)
            #pragma unroll
            for (int i = 0; i < 4; i++) acc[f][nf][i] = 0.f;

    load_stage(sb, 0, 0, tid, ag, bg); CP_COMMIT();
    load_stage(sb, 1, 1, tid, ag, bg); CP_COMMIT();

    #pragma unroll 1
    for (int kt3 = 0; kt3 < 15; kt3 += 3) {
        gemm128_step<0>(sb, kt3 + 0, tid, ag, bg, offA, offB, acc);
        gemm128_step<1>(sb, kt3 + 1, tid, ag, bg, offA, offB, acc);
        gemm128_step<2>(sb, kt3 + 2, tid, ag, bg, offA, offB, acc);
    }
    gemm128_step<0>(sb, 15, tid, ag, bg, offA, offB, acc);
}

// ---------------------------------------------------------------------------
// GEMM core 64x128 (for oproj), static-stage mainloop.
// ---------------------------------------------------------------------------
#define STG64 24576
#define GEMM64_SMEM (3 * STG64)

__device__ __forceinline__ void load_stage64(
    uint32_t sb, int s, int kt, int tid,
    const char* ag, const char* bg)
{
    const uint32_t st = sb + (uint32_t)s * STG64;
    const int c16 = (tid & 7) * 16;
    const size_t gk = (size_t)kt * 128 + (size_t)c16;
    #pragma unroll
    for (int p = 0; p < 2; ++p) {
        int row = p * 32 + (tid >> 3);
        uint32_t so = SWZ128((uint32_t)(row * 128 + c16));
        cp16(st + so, ag + (size_t)row * 2048 + gk);
    }
    #pragma unroll
    for (int p = 0; p < 4; ++p) {
        int row = p * 32 + (tid >> 3);
        uint32_t so = SWZ128((uint32_t)(row * 128 + c16));
        cp16(st + 8192 + so, bg + (size_t)row * 2048 + gk);
    }
}

template <int S>
__device__ __forceinline__ void gemm64_step(
    uint32_t sb, int kt, int tid,
    const char* ag, const char* bg,
    const uint32_t offA[2], const uint32_t offB[2],
    float acc[2][4][4])
{
    CP_WAIT1();
    __syncthreads();
    if (kt + 2 < 16)
        load_stage64(sb, (S + 2) % 3, kt + 2, tid, ag, bg);
    CP_COMMIT();

    const uint32_t base = sb + (uint32_t)(S * STG64);
    #pragma unroll
    for (int s16 = 0; s16 < 4; ++s16) {
        const uint32_t sx = (uint32_t)(s16 * 32);
        uint32_t a0[4], a1[4], b0[4], b1[4];
        ldmx4(a0, base + (offA[0] ^ sx));
        ldmx4(a1, base + (offA[1] ^ sx));
        ldmx4(b0, base + 8192 + (offB[0] ^ sx));
        ldmx4(b1, base + 8192 + (offB[1] ^ sx));
        uint32_t* aa[2] = {a0, a1};
        uint32_t* bb[2] = {b0, b1};
        #pragma unroll
        for (int f = 0; f < 2; ++f)
            #pragma unroll
            for (int nf = 0; nf < 4; ++nf)
                mmah(acc[f][nf], aa[f],
                     bb[nf >> 1][(nf & 1) * 2], bb[nf >> 1][(nf & 1) * 2 + 1]);
    }
}

__device__ __forceinline__ void gemm_core_64x128_h(
    uint32_t sb, const char* ag, const char* bg, float acc[2][4][4])
{
    const int tid = threadIdx.x;
    const int warp = tid >> 5, lane = tid & 31;
    const int wm = (warp & 1) * 32;
    const int wn = (warp >> 1) * 32;

    uint32_t offA[2], offB[2];
    {
        const int rbA = (lane & 7) + ((lane >> 3) & 1) * 8;
        const int cA  = (lane >> 4) & 1;
        const int rbB = (lane & 7) + ((lane >> 4) & 1) * 8;
        const int cB  = (lane >> 3) & 1;
        #pragma unroll
        for (int f = 0; f < 2; ++f) {
            offA[f] = SWZ128((uint32_t)((wm + f*16 + rbA) * 128 + cA * 16));
            offB[f] = SWZ128((uint32_t)((wn + f*16 + rbB) * 128 + cB * 16));
        }
    }
    #pragma unroll
    for (int f = 0; f < 2; f++)
        #pragma unroll
        for (int nf = 0; nf < 4; nf++)
            #pragma unroll
            for (int i = 0; i < 4; i++) acc[f][nf][i] = 0.f;

    load_stage64(sb, 0, 0, tid, ag, bg); CP_COMMIT();
    load_stage64(sb, 1, 1, tid, ag, bg); CP_COMMIT();

    #pragma unroll 1
    for (int kt3 = 0; kt3 < 15; kt3 += 3) {
        gemm64_step<0>(sb, kt3 + 0, tid, ag, bg, offA, offB, acc);
        gemm64_step<1>(sb, kt3 + 1, tid, ag, bg, offA, offB, acc);
        gemm64_step<2>(sb, kt3 + 2, tid, ag, bg, offA, offB, acc);
    }
    gemm64_step<0>(sb, 15, tid, ag, bg, offA, offB, acc);
}

// ---------------------------------------------------------------------------
// QKV projection: merged GEMM C[8192 x 3072] = X * W_all^T
// ---------------------------------------------------------------------------
__global__ __launch_bounds__(256, 2) void qkv_mma_kernel(
    const float* __restrict__ bq, const float* __restrict__ bk,
    const float* __restrict__ bv)
{
    extern __shared__ char smem[];
    const uint32_t sb = smem_to_u32(smem);
    const int tid = threadIdx.x;
    const int m0 = blockIdx.x * 128;
    const int n0 = blockIdx.y * 128;

    const char* ag = (const char*)(g_x16 + (size_t)m0 * EE);
    const char* bg = (const char*)(g_w16 + (size_t)n0 * EE);

    float acc[2][8][4];
    gemm_core_128x128_h(sb, ag, bg, acc);

    const int warp = tid >> 5, lane = tid & 31;
    const int wm = (warp & 3) * 32, wn = (warp >> 2) * 64;
    const int r = lane >> 2, cp2 = (lane & 3) * 2;

    const int z = (n0 + wn) >> 6;               // one head per warp
    const int which = z >> 4, h = z & 15;
    const float* bp = (which == 0 ? bq : which == 1 ? bk : bv) + h * DD;
    __half* op = (which == 0 ? g_q16 : which == 1 ? g_k16 : g_v16);
    const float osc = (which == 0) ? 0.125f * 1.4426950408889634f : 1.0f;

    #pragma unroll
    for (int f = 0; f < 2; ++f) {
        #pragma unroll
        for (int half = 0; half < 2; ++half) {
            int m = m0 + wm + f * 16 + r + half * 8;
            int b = m >> 11, s = m & 2047;
            size_t rowoff = (((size_t)b * HH + h) * SS + s) * DD;
            #pragma unroll
            for (int nf = 0; nf < 8; ++nf) {
                int d = nf * 8 + cp2;
                float v0 = (acc[f][nf][half * 2 + 0] + bp[d]) * osc;
                float v1 = (acc[f][nf][half * 2 + 1] + bp[d + 1]) * osc;
                *(uint32_t*)(op + rowoff + d) = cvt_pair(v0, v1);
            }
        }
    }
}

// ---------------------------------------------------------------------------
// Output projection: y[8192x1024] = O_cat * wo + bo, 64x128 tiles, grid (128, 8)
// ---------------------------------------------------------------------------
__global__ __launch_bounds__(256, 2) void oproj_mma_kernel(
    const float* __restrict__ bo, float* __restrict__ y)
{
    extern __shared__ char smem[];
    const uint32_t sb = smem_to_u32(smem);
    const int tid = threadIdx.x;
    const int m0 = blockIdx.x * 64;
    const int n0 = blockIdx.y * 128;

    const char* ag = (const char*)(g_o16 + (size_t)m0 * EE);
    const char* bg = (const char*)(g_wo16 + (size_t)n0 * EE);

    float acc[2][4][4];
    gemm_core_64x128_h(sb, ag, bg, acc);

    const int warp = tid >> 5, lane = tid & 31;
    const int wm = (warp & 1) * 32, wn = (warp >> 1) * 32;
    const int r = lane >> 2, cp2 = (lane & 3) * 2;
    #pragma unroll
    for (int f = 0; f < 2; ++f) {
        #pragma unroll
        for (int half = 0; half < 2; ++half) {
            int m = m0 + wm + f * 16 + r + half * 8;
            float* row = y + (size_t)m * EE + n0 + wn;
            #pragma unroll
            for (int nf = 0; nf < 4; ++nf) {
                int col = nf * 8 + cp2;
                float2 v;
                v.x = acc[f][nf][half * 2 + 0] + bo[n0 + wn + col];
                v.y = acc[f][nf][half * 2 + 1] + bo[n0 + wn + col + 1];
                *(float2*)(row + col) = v;
            }
        }
    }
}

// ---------------------------------------------------------------------------
// Flash attention: R14 structure + static-stage mainloop (unroll-by-3,
// stage as template constant; prefetch stage (ct+3)%3 == S folds too).
// 3 KV stages + dedicated Q region, 64KB, 2 CTAs/SM, long blocks first.
// ---------------------------------------------------------------------------
#define AT_STAGE 16384
#define AT_SMEM  (4 * AT_STAGE)

__device__ __forceinline__ void attn_load_kv(
    uint32_t sb, int stage, int ct, int tid,
    const char* kg, const char* vg)
{
    const uint32_t st = sb + (uint32_t)stage * AT_STAGE;
    const int col0 = ct * 64;
    #pragma unroll
    for (int p = 0; p < 2; ++p) {
        int idx = p * 256 + tid;
        int r = idx >> 3, c16 = (idx & 7) * 16;
        uint32_t so = SWZ128((uint32_t)(r * 128 + c16));
        size_t g = (size_t)(col0 + r) * 128 + c16;
        cp16(st + so,        kg + g);
        cp16(st + 8192 + so, vg + g);
    }
}

struct AttnState {
    float o[8][4];
    float lacc[4];
    float mprev0, mprev1;
};

template <int S>
__device__ __forceinline__ void attn_step(
    uint32_t sb, int ct, int nct, int tid,
    const char* kg, const char* vg,
    const uint32_t qf[4][4], AttnState& st,
    int row0, int wm, int rbA, int cA, int rbB, int cB,
    int lc2, int r0g)
{
    CP_WAIT2();
    __syncthreads();
    const uint32_t base = sb + (uint32_t)(S * AT_STAGE);
    const uint32_t ONE2 = 0x3C003C00u;

    const bool active = (ct * 64) <= (row0 + wm + 15);
    if (active) {
        // ---- S = Q K^T ----
        float s[8][4];
        #pragma unroll
        for (int nf = 0; nf < 8; nf++)
            #pragma unroll
            for (int i = 0; i < 4; i++) s[nf][i] = 0.f;

        #pragma unroll
        for (int c = 0; c < 4; ++c) {
            uint32_t kh[4][4];
            #pragma unroll
            for (int g = 0; g < 4; ++g) {
                uint32_t off = SWZ128((uint32_t)((g * 16 + rbB) * 128 + (c * 2 + cB) * 16));
                ldmx4(kh[g], base + off);
            }
            #pragma unroll
            for (int nf = 0; nf < 8; ++nf) {
                int g = nf >> 1, i = (nf & 1) * 2;
                mmah(s[nf], qf[c], kh[g][i], kh[g][i + 1]);
            }
        }

        // ---- causal mask ----
        if (ct * 64 + 63 > row0 + wm) {
            #pragma unroll
            for (int nf = 0; nf < 8; ++nf) {
                int cg = ct * 64 + nf * 8 + lc2;
                if (cg     > r0g)     s[nf][0] = -CUDART_INF_F;
                if (cg + 1 > r0g)     s[nf][1] = -CUDART_INF_F;
                if (cg     > r0g + 8) s[nf][2] = -CUDART_INF_F;
                if (cg + 1 > r0g + 8) s[nf][3] = -CUDART_INF_F;
            }
        }

        // ---- row max ----
        float mt0 = -CUDART_INF_F, mt1 = -CUDART_INF_F;
        #pragma unroll
        for (int nf = 0; nf < 8; ++nf) {
            mt0 = fmaxf(mt0, fmaxf(s[nf][0], s[nf][1]));
            mt1 = fmaxf(mt1, fmaxf(s[nf][2], s[nf][3]));
        }
        mt0 = fmaxf(mt0, __shfl_xor_sync(0xffffffffu, mt0, 1));
        mt0 = fmaxf(mt0, __shfl_xor_sync(0xffffffffu, mt0, 2));
        mt1 = fmaxf(mt1, __shfl_xor_sync(0xffffffffu, mt1, 1));
        mt1 = fmaxf(mt1, __shfl_xor_sync(0xffffffffu, mt1, 2));

        float mn0 = fmaxf(st.mprev0, mt0);
        float mn1 = fmaxf(st.mprev1, mt1);
        float a0 = exp2f(st.mprev0 - mn0);
        float a1 = exp2f(st.mprev1 - mn1);
        st.mprev0 = mn0; st.mprev1 = mn1;

        st.lacc[0] *= a0; st.lacc[1] *= a0;
        st.lacc[2] *= a1; st.lacc[3] *= a1;
        #pragma unroll
        for (int nf = 0; nf < 8; ++nf) {
            st.o[nf][0] *= a0; st.o[nf][1] *= a0;
            st.o[nf][2] *= a1; st.o[nf][3] *= a1;
        }

        // ---- P = exp2(s - m) in f16x2 fragments ----
        uint32_t pf[4][4];
        #pragma unroll
        for (int kk = 0; kk < 4; ++kk) {
            pf[kk][0] = h2exp2(cvtpair_f2h(s[2*kk][0]   - mn0, s[2*kk][1]   - mn0));
            pf[kk][1] = h2exp2(cvtpair_f2h(s[2*kk][2]   - mn1, s[2*kk][3]   - mn1));
            pf[kk][2] = h2exp2(cvtpair_f2h(s[2*kk+1][0] - mn0, s[2*kk+1][1] - mn0));
            pf[kk][3] = h2exp2(cvtpair_f2h(s[2*kk+1][2] - mn1, s[2*kk+1][3] - mn1));
        }

        // ---- row sums via ones-MMA ----
        #pragma unroll
        for (int kk = 0; kk < 4; ++kk)
            mmah(st.lacc, pf[kk], ONE2, ONE2);

        // ---- O += P V ----
        #pragma unroll
        for (int kk = 0; kk < 4; ++kk) {
            #pragma unroll
            for (int dd = 0; dd < 4; ++dd) {
                uint32_t vh[4];
                uint32_t off = SWZ128((uint32_t)((kk * 16 + rbA) * 128 + (dd * 2 + cA) * 16));
                ldmx4t(vh, base + 8192 + off);
                #pragma unroll
                for (int j = 0; j < 2; ++j) {
                    int nf = dd * 2 + j;
                    mmah(st.o[nf], pf[kk], vh[j * 2], vh[j * 2 + 1]);
                }
            }
        }
    }

    __syncthreads();
    if (ct + 3 < nct)
        attn_load_kv(sb, S, ct + 3, tid, kg, vg);   // (ct+3)%3 == S
    CP_COMMIT();
}

__global__ __launch_bounds__(256, 2) void attn_mma_kernel()
{
    extern __shared__ char smem[];
    const uint32_t sb = smem_to_u32(smem);
    const uint32_t qb = sb + 3 * AT_STAGE;     // dedicated Q region
    const int tid = threadIdx.x;
    const int warp = tid >> 5, lane = tid & 31;
    const int rt = (int)gridDim.x - 1 - (int)blockIdx.x;  // long blocks first
    const int bh = blockIdx.y;
    const int row0 = rt * 128;
    const int wm = warp * 16;

    const char* qg = (const char*)(g_q16 + (size_t)bh * SS * DD);
    const char* kg = (const char*)(g_k16 + (size_t)bh * SS * DD);
    const char* vg = (const char*)(g_v16 + (size_t)bh * SS * DD);

    const int nct = 2 * rt + 2;

    // ---- overlapped prologue: Q (group0) then KV stages 0..2 (groups 1..3)
    #pragma unroll
    for (int p = 0; p < 4; ++p) {
        int cc = p * 256 + tid;
        int rr = cc >> 3, c = (cc & 7) * 16;
        uint32_t so = SWZ128((uint32_t)(rr * 128 + c));
        cp16(qb + so, qg + (size_t)(row0 + rr) * 128 + c);
    }
    CP_COMMIT();                                   // g0: Q
    attn_load_kv(sb, 0, 0, tid, kg, vg); CP_COMMIT();       // g1
    if (nct > 1) attn_load_kv(sb, 1, 1, tid, kg, vg);
    CP_COMMIT();                                   // g2
    if (nct > 2) attn_load_kv(sb, 2, 2, tid, kg, vg);
    CP_COMMIT();                                   // g3

    CP_WAIT3();            // Q complete
    __syncthreads();

    const int rbA = (lane & 7) + ((lane >> 3) & 1) * 8;
    const int cA  = (lane >> 4) & 1;
    uint32_t qf[4][4];
    #pragma unroll
    for (int c = 0; c < 4; ++c) {
        uint32_t off = SWZ128((uint32_t)((wm + rbA) * 128 + (c * 2 + cA) * 16));
        ldmx4(qf[c], qb + off);
    }

    AttnState st;
    #pragma unroll
    for (int nf = 0; nf < 8; nf++)
        #pragma unroll
        for (int i = 0; i < 4; i++) st.o[nf][i] = 0.f;
    st.lacc[0] = st.lacc[1] = st.lacc[2] = st.lacc[3] = 0.f;
    st.mprev0 = -CUDART_INF_F; st.mprev1 = -CUDART_INF_F;

    const int rbB = (lane & 7) + ((lane >> 4) & 1) * 8;
    const int cB  = (lane >> 3) & 1;
    const int lr  = lane >> 2;
    const int lc2 = (lane & 3) * 2;
    const int r0g = row0 + wm + lr;

    // static-stage mainloop: triples + remainder (nct % 3 ∈ {0,1,2})
    const int nct3 = nct - (nct % 3);
    #pragma unroll 1
    for (int ct3 = 0; ct3 < nct3; ct3 += 3) {
        attn_step<0>(sb, ct3 + 0, nct, tid, kg, vg, qf, st,
                     row0, wm, rbA, cA, rbB, cB, lc2, r0g);
        attn_step<1>(sb, ct3 + 1, nct, tid, kg, vg, qf, st,
                     row0, wm, rbA, cA, rbB, cB, lc2, r0g);
        attn_step<2>(sb, ct3 + 2, nct, tid, kg, vg, qf, st,
                     row0, wm, rbA, cA, rbB, cB, lc2, r0g);
    }
    if (nct % 3 >= 1)
        attn_step<0>(sb, nct3, nct, tid, kg, vg, qf, st,
                     row0, wm, rbA, cA, rbB, cB, lc2, r0g);
    if (nct % 3 == 2)
        attn_step<1>(sb, nct3 + 1, nct, tid, kg, vg, qf, st,
                     row0, wm, rbA, cA, rbB, cB, lc2, r0g);

    float inv0 = 1.f / st.lacc[0];
    float inv1 = 1.f / st.lacc[2];

    const int b = bh >> 4, h = bh & 15;
    const size_t m0G = (size_t)b * SS + (size_t)(row0 + wm + lr);
    __half* o0 = g_o16 + m0G * EE + h * DD;
    __half* o1 = o0 + (size_t)8 * EE;
    #pragma unroll
    for (int nf = 0; nf < 8; ++nf) {
        int col = nf * 8 + lc2;
        *(uint32_t*)(o0 + col) = cvt_pair(st.o[nf][0] * inv0, st.o[nf][1] * inv0);
        *(uint32_t*)(o1 + col) = cvt_pair(st.o[nf][2] * inv1, st.o[nf][3] * inv1);
    }
}

// ---------------------------------------------------------------------------
extern "C" void kernel_launch(void* const* d_in, const int* in_sizes, int n_in,
                              void* d_out, int out_size)
{
    const float* x  = (const float*)d_in[0];
    const float* wq = (const float*)d_in[1];
    const float* bq = (const float*)d_in[2];
    const float* wk = (const float*)d_in[3];
    const float* bk = (const float*)d_in[4];
    const float* wv = (const float*)d_in[5];
    const float* bv = (const float*)d_in[6];
    const float* wo = (const float*)d_in[7];
    const float* bo = (const float*)d_in[8];
    float* y = (float*)d_out;

    (void)in_sizes; (void)n_in; (void)out_size;

    cudaFuncSetAttribute(qkv_mma_kernel, cudaFuncAttributeMaxDynamicSharedMemorySize,
                         GEMM_SMEM);
    cudaFuncSetAttribute(oproj_mma_kernel, cudaFuncAttributeMaxDynamicSharedMemorySize,
                         GEMM64_SMEM);
    cudaFuncSetAttribute(attn_mma_kernel, cudaFuncAttributeMaxDynamicSharedMemorySize,
                         AT_SMEM);

    // 1) merged fp32 -> fp16 prep (x, W_all^T, wo^T)
    prep_kernel<<<5120, 256>>>(x, wq, wk, wv, wo);

    // 2) QKV projection: merged GEMM [8192 x 3072], static-stage mainloop
    qkv_mma_kernel<<<dim3(64, 24), 256, GEMM_SMEM>>>(bq, bk, bv);

    // 3) Flash attention (static-stage mainloop)
    attn_mma_kernel<<<dim3(16, 64), 256, AT_SMEM>>>();

    // 4) Output projection: 64x128 tiles, static-stage mainloop
    oproj_mma_kernel<<<dim3(128, 8), 256, GEMM64_SMEM>>>(bo, y);
}

// round 17
// speedup vs baseline: 1.0150x; 1.0150x over previous
#include <cuda_runtime.h>
#include <cuda_fp16.h>
#include <math_constants.h>
#include <cstdint>

#define BB 4
#define SS 2048
#define EE 1024
#define HH 16
#define DD 64
#define MM (BB*SS)   // 8192

// ---------------------------------------------------------------------------
// Device-global scratch (allocation-free rule) — all fp16
// ---------------------------------------------------------------------------
__device__ __align__(16) __half g_x16[MM*EE];
__device__ __align__(16) __half g_w16[48*DD*EE];    // [z*64+d][e] == W_all^T
__device__ __align__(16) __half g_wo16[EE*EE];      // [n][k] (wo transposed)
__device__ __align__(16) __half g_q16[BB*HH*SS*DD]; // [bh][s][d], pre-scaled by 1/sqrt(D)*log2e
__device__ __align__(16) __half g_k16[BB*HH*SS*DD];
__device__ __align__(16) __half g_v16[BB*HH*SS*DD];
__device__ __align__(16) __half g_o16[MM*EE];       // [m][h*64+d]

// ---------------------------------------------------------------------------
// mma.sync / ldmatrix / cp.async helpers
// ---------------------------------------------------------------------------
__device__ __forceinline__ uint32_t smem_to_u32(const void* p) {
    uint32_t a;
    asm("{ .reg .u64 t; cvta.to.shared.u64 t, %1; cvt.u32.u64 %0, t; }"
        : "=r"(a) : "l"(p));
    return a;
}
__device__ __forceinline__ void cp16(uint32_t saddr, const void* gaddr) {
    asm volatile("cp.async.cg.shared.global [%0], [%1], 16;"
                 :: "r"(saddr), "l"(gaddr));
}
#define CP_COMMIT() asm volatile("cp.async.commit_group;" ::: "memory")
#define CP_WAIT1()  asm volatile("cp.async.wait_group 1;" ::: "memory")
#define CP_WAIT2()  asm volatile("cp.async.wait_group 2;" ::: "memory")
#define CP_WAIT3()  asm volatile("cp.async.wait_group 3;" ::: "memory")
#define CP_WAIT0()  asm volatile("cp.async.wait_group 0;" ::: "memory")

__device__ __forceinline__ void ldmx4(uint32_t* r, uint32_t addr) {
    asm volatile("ldmatrix.sync.aligned.m8n8.x4.shared.b16 {%0,%1,%2,%3}, [%4];"
        : "=r"(r[0]), "=r"(r[1]), "=r"(r[2]), "=r"(r[3]) : "r"(addr));
}
__device__ __forceinline__ void ldmx4t(uint32_t* r, uint32_t addr) {
    asm volatile("ldmatrix.sync.aligned.m8n8.x4.trans.shared.b16 {%0,%1,%2,%3}, [%4];"
        : "=r"(r[0]), "=r"(r[1]), "=r"(r[2]), "=r"(r[3]) : "r"(addr));
}
__device__ __forceinline__ void mmah(float* c, const uint32_t* a,
                                     uint32_t b0, uint32_t b1) {
    asm volatile("mma.sync.aligned.m16n8k16.row.col.f32.f16.f16.f32 "
        "{%0,%1,%2,%3}, {%4,%5,%6,%7}, {%8,%9}, {%0,%1,%2,%3};"
        : "+f"(c[0]), "+f"(c[1]), "+f"(c[2]), "+f"(c[3])
        : "r"(a[0]), "r"(a[1]), "r"(a[2]), "r"(a[3]), "r"(b0), "r"(b1));
}

#define SWZ128(off) ((off) ^ (((off) >> 3) & 0x70))   // 128B rows

__device__ __forceinline__ uint32_t pckh(__half a, __half b) {
    return ((uint32_t)__half_as_ushort(b) << 16) | (uint32_t)__half_as_ushort(a);
}
__device__ __forceinline__ uint32_t cvt_pair(float v0, float v1) {
    return pckh(__float2half_rn(v0), __float2half_rn(v1));
}
__device__ __forceinline__ uint32_t cvtpair_f2h(float v0, float v1) {
    uint32_t r;
    asm("cvt.rn.f16x2.f32 %0, %1, %2;" : "=r"(r) : "f"(v1), "f"(v0));
    return r;
}
__device__ __forceinline__ uint32_t h2exp2(uint32_t x) {
    uint32_t r;
    asm("ex2.approx.f16x2 %0, %1;" : "=r"(r) : "r"(x));
    return r;
}

// ---------------------------------------------------------------------------
// Merged prep kernel: fp32 -> fp16 for x, W_all (transposed), wo (transposed)
// ---------------------------------------------------------------------------
__global__ __launch_bounds__(256) void prep_kernel(
    const float* __restrict__ x,
    const float* __restrict__ wq, const float* __restrict__ wk,
    const float* __restrict__ wv, const float* __restrict__ wo)
{
    __shared__ float t[64][65];
    const int bid = blockIdx.x;
    const int tid = threadIdx.x;

    if (bid < 4096) {
        size_t i = ((size_t)bid * 256 + tid) * 8;
        float4 v0 = *(const float4*)(x + i);
        float4 v1 = *(const float4*)(x + i + 4);
        uint4 u;
        u.x = cvt_pair(v0.x, v0.y); u.y = cvt_pair(v0.z, v0.w);
        u.z = cvt_pair(v1.x, v1.y); u.w = cvt_pair(v1.z, v1.w);
        *(uint4*)(g_x16 + i) = u;
    } else if (bid < 4096 + 768) {
        const int tt = bid - 4096;
        const int e0 = (tt & 15) * 64;
        const int z = tt >> 4;
        const int which = z >> 4, h = z & 15;
        const float* W = (which == 0 ? wq : which == 1 ? wk : wv) + (size_t)h * EE * DD;
        #pragma unroll
        for (int q = 0; q < 4; q++) {
            int idx = q * 256 + tid;
            int r = idx >> 4, c = (idx & 15) * 4;
            float4 v = *(const float4*)(W + (size_t)(e0 + r) * DD + c);
            t[r][c] = v.x; t[r][c+1] = v.y; t[r][c+2] = v.z; t[r][c+3] = v.w;
        }
        __syncthreads();
        #pragma unroll
        for (int q = 0; q < 4; q++) {
            int idx = q * 256 + tid;
            int d = idx >> 4, e = (idx & 15) * 4;
            size_t o = ((size_t)z * DD + d) * EE + e0 + e;
            *(uint32_t*)(g_w16 + o)     = cvt_pair(t[e][d],   t[e+1][d]);
            *(uint32_t*)(g_w16 + o + 2) = cvt_pair(t[e+2][d], t[e+3][d]);
        }
    } else {
        const int tt = bid - (4096 + 768);
        const int k0 = (tt & 15) * 64;
        const int n0 = (tt >> 4) * 64;
        #pragma unroll
        for (int q = 0; q < 4; q++) {
            int idx = q * 256 + tid;
            int r = idx >> 4, c = (idx & 15) * 4;
            float4 v = *(const float4*)(wo + (size_t)(k0 + r) * EE + n0 + c);
            t[r][c] = v.x; t[r][c+1] = v.y; t[r][c+2] = v.z; t[r][c+3] = v.w;
        }
        __syncthreads();
        #pragma unroll
        for (int q = 0; q < 4; q++) {
            int idx = q * 256 + tid;
            int d = idx >> 4, e = (idx & 15) * 4;
            size_t o = (size_t)(n0 + d) * EE + k0 + e;
            *(uint32_t*)(g_wo16 + o)     = cvt_pair(t[e][d],   t[e+1][d]);
            *(uint32_t*)(g_wo16 + o + 2) = cvt_pair(t[e+2][d], t[e+3][d]);
        }
    }
}

// ---------------------------------------------------------------------------
// GEMM core 128x128, fp16 single-pass (for qkv). Static-stage mainloop.
// ---------------------------------------------------------------------------
#define STAGE_BYTES 32768
#define GEMM_SMEM   (3 * STAGE_BYTES)

__device__ __forceinline__ void load_stage(
    uint32_t sb, int s, int kt, int tid,
    const char* ag, const char* bg)
{
    const uint32_t st = sb + (uint32_t)s * STAGE_BYTES;
    const int c16 = (tid & 7) * 16;
    const size_t gk = (size_t)kt * 128 + (size_t)c16;
    #pragma unroll
    for (int p = 0; p < 4; ++p) {
        int row = p * 32 + (tid >> 3);
        uint32_t so = SWZ128((uint32_t)(row * 128 + c16));
        size_t g = (size_t)row * 2048 + gk;
        cp16(st + so,         ag + g);
        cp16(st + 16384 + so, bg + g);
    }
}

template <int S>
__device__ __forceinline__ void gemm128_step(
    uint32_t sb, int kt, int tid,
    const char* ag, const char* bg,
    const uint32_t offA[2], const uint32_t offB[4],
    float acc[2][8][4])
{
    CP_WAIT1();
    __syncthreads();
    if (kt + 2 < 16)
        load_stage(sb, (S + 2) % 3, kt + 2, tid, ag, bg);
    CP_COMMIT();

    const uint32_t base = sb + (uint32_t)(S * STAGE_BYTES);
    #pragma unroll
    for (int s16 = 0; s16 < 4; ++s16) {
        const uint32_t sx = (uint32_t)(s16 * 32);
        uint32_t a0[4], a1[4];
        ldmx4(a0, base + (offA[0] ^ sx));
        ldmx4(a1, base + (offA[1] ^ sx));
        uint32_t b[4][4];
        #pragma unroll
        for (int g = 0; g < 4; ++g)
            ldmx4(b[g], base + 16384 + (offB[g] ^ sx));
        uint32_t* aa[2] = {a0, a1};
        #pragma unroll
        for (int f = 0; f < 2; ++f)
            #pragma unroll
            for (int nf = 0; nf < 8; ++nf)
                mmah(acc[f][nf], aa[f],
                     b[nf >> 1][(nf & 1) * 2], b[nf >> 1][(nf & 1) * 2 + 1]);
    }
}

__device__ __forceinline__ void gemm_core_128x128_h(
    uint32_t sb, const char* ag, const char* bg, float acc[2][8][4])
{
    const int tid = threadIdx.x;
    const int warp = tid >> 5, lane = tid & 31;
    const int wm = (warp & 3) * 32;
    const int wn = (warp >> 2) * 64;

    uint32_t offA[2], offB[4];
    {
        const int rbA = (lane & 7) + ((lane >> 3) & 1) * 8;
        const int cA  = (lane >> 4) & 1;
        const int rbB = (lane & 7) + ((lane >> 4) & 1) * 8;
        const int cB  = (lane >> 3) & 1;
        #pragma unroll
        for (int f = 0; f < 2; ++f)
            offA[f] = SWZ128((uint32_t)((wm + f*16 + rbA) * 128 + cA * 16));
        #pragma unroll
        for (int g = 0; g < 4; ++g)
            offB[g] = SWZ128((uint32_t)((wn + g*16 + rbB) * 128 + cB * 16));
    }
    #pragma unroll
    for (int f = 0; f < 2; f++)
        #pragma unroll
        for (int nf = 0; nf < 8; nf++)
            #pragma unroll
            for (int i = 0; i < 4; i++) acc[f][nf][i] = 0.f;

    load_stage(sb, 0, 0, tid, ag, bg); CP_COMMIT();
    load_stage(sb, 1, 1, tid, ag, bg); CP_COMMIT();

    #pragma unroll 1
    for (int kt3 = 0; kt3 < 15; kt3 += 3) {
        gemm128_step<0>(sb, kt3 + 0, tid, ag, bg, offA, offB, acc);
        gemm128_step<1>(sb, kt3 + 1, tid, ag, bg, offA, offB, acc);
        gemm128_step<2>(sb, kt3 + 2, tid, ag, bg, offA, offB, acc);
    }
    gemm128_step<0>(sb, 15, tid, ag, bg, offA, offB, acc);
}

// ---------------------------------------------------------------------------
// GEMM core 64x128 (for oproj), static-stage mainloop.
// ---------------------------------------------------------------------------
#define STG64 24576
#define GEMM64_SMEM (3 * STG64)

__device__ __forceinline__ void load_stage64(
    uint32_t sb, int s, int kt, int tid,
    const char* ag, const char* bg)
{
    const uint32_t st = sb + (uint32_t)s * STG64;
    const int c16 = (tid & 7) * 16;
    const size_t gk = (size_t)kt * 128 + (size_t)c16;
    #pragma unroll
    for (int p = 0; p < 2; ++p) {
        int row = p * 32 + (tid >> 3);
        uint32_t so = SWZ128((uint32_t)(row * 128 + c16));
        cp16(st + so, ag + (size_t)row * 2048 + gk);
    }
    #pragma unroll
    for (int p = 0; p < 4; ++p) {
        int row = p * 32 + (tid >> 3);
        uint32_t so = SWZ128((uint32_t)(row * 128 + c16));
        cp16(st + 8192 + so, bg + (size_t)row * 2048 + gk);
    }
}

template <int S>
__device__ __forceinline__ void gemm64_step(
    uint32_t sb, int kt, int tid,
    const char* ag, const char* bg,
    const uint32_t offA[2], const uint32_t offB[2],
    float acc[2][4][4])
{
    CP_WAIT1();
    __syncthreads();
    if (kt + 2 < 16)
        load_stage64(sb, (S + 2) % 3, kt + 2, tid, ag, bg);
    CP_COMMIT();

    const uint32_t base = sb + (uint32_t)(S * STG64);
    #pragma unroll
    for (int s16 = 0; s16 < 4; ++s16) {
        const uint32_t sx = (uint32_t)(s16 * 32);
        uint32_t a0[4], a1[4], b0[4], b1[4];
        ldmx4(a0, base + (offA[0] ^ sx));
        ldmx4(a1, base + (offA[1] ^ sx));
        ldmx4(b0, base + 8192 + (offB[0] ^ sx));
        ldmx4(b1, base + 8192 + (offB[1] ^ sx));
        uint32_t* aa[2] = {a0, a1};
        uint32_t* bb[2] = {b0, b1};
        #pragma unroll
        for (int f = 0; f < 2; ++f)
            #pragma unroll
            for (int nf = 0; nf < 4; ++nf)
                mmah(acc[f][nf], aa[f],
                     bb[nf >> 1][(nf & 1) * 2], bb[nf >> 1][(nf & 1) * 2 + 1]);
    }
}

__device__ __forceinline__ void gemm_core_64x128_h(
    uint32_t sb, const char* ag, const char* bg, float acc[2][4][4])
{
    const int tid = threadIdx.x;
    const int warp = tid >> 5, lane = tid & 31;
    const int wm = (warp & 1) * 32;
    const int wn = (warp >> 1) * 32;

    uint32_t offA[2], offB[2];
    {
        const int rbA = (lane & 7) + ((lane >> 3) & 1) * 8;
        const int cA  = (lane >> 4) & 1;
        const int rbB = (lane & 7) + ((lane >> 4) & 1) * 8;
        const int cB  = (lane >> 3) & 1;
        #pragma unroll
        for (int f = 0; f < 2; ++f) {
            offA[f] = SWZ128((uint32_t)((wm + f*16 + rbA) * 128 + cA * 16));
            offB[f] = SWZ128((uint32_t)((wn + f*16 + rbB) * 128 + cB * 16));
        }
    }
    #pragma unroll
    for (int f = 0; f < 2; f++)
        #pragma unroll
        for (int nf = 0; nf < 4; nf++)
            #pragma unroll
            for (int i = 0; i < 4; i++) acc[f][nf][i] = 0.f;

    load_stage64(sb, 0, 0, tid, ag, bg); CP_COMMIT();
    load_stage64(sb, 1, 1, tid, ag, bg); CP_COMMIT();

    #pragma unroll 1
    for (int kt3 = 0; kt3 < 15; kt3 += 3) {
        gemm64_step<0>(sb, kt3 + 0, tid, ag, bg, offA, offB, acc);
        gemm64_step<1>(sb, kt3 + 1, tid, ag, bg, offA, offB, acc);
        gemm64_step<2>(sb, kt3 + 2, tid, ag, bg, offA, offB, acc);
    }
    gemm64_step<0>(sb, 15, tid, ag, bg, offA, offB, acc);
}

// ---------------------------------------------------------------------------
// QKV projection: merged GEMM C[8192 x 3072] = X * W_all^T
// ---------------------------------------------------------------------------
__global__ __launch_bounds__(256, 2) void qkv_mma_kernel(
    const float* __restrict__ bq, const float* __restrict__ bk,
    const float* __restrict__ bv)
{
    extern __shared__ char smem[];
    const uint32_t sb = smem_to_u32(smem);
    const int tid = threadIdx.x;
    const int m0 = blockIdx.x * 128;
    const int n0 = blockIdx.y * 128;

    const char* ag = (const char*)(g_x16 + (size_t)m0 * EE);
    const char* bg = (const char*)(g_w16 + (size_t)n0 * EE);

    float acc[2][8][4];
    gemm_core_128x128_h(sb, ag, bg, acc);

    const int warp = tid >> 5, lane = tid & 31;
    const int wm = (warp & 3) * 32, wn = (warp >> 2) * 64;
    const int r = lane >> 2, cp2 = (lane & 3) * 2;

    const int z = (n0 + wn) >> 6;               // one head per warp
    const int which = z >> 4, h = z & 15;
    const float* bp = (which == 0 ? bq : which == 1 ? bk : bv) + h * DD;
    __half* op = (which == 0 ? g_q16 : which == 1 ? g_k16 : g_v16);
    const float osc = (which == 0) ? 0.125f * 1.4426950408889634f : 1.0f;

    #pragma unroll
    for (int f = 0; f < 2; ++f) {
        #pragma unroll
        for (int half = 0; half < 2; ++half) {
            int m = m0 + wm + f * 16 + r + half * 8;
            int b = m >> 11, s = m & 2047;
            size_t rowoff = (((size_t)b * HH + h) * SS + s) * DD;
            #pragma unroll
            for (int nf = 0; nf < 8; ++nf) {
                int d = nf * 8 + cp2;
                float v0 = (acc[f][nf][half * 2 + 0] + bp[d]) * osc;
                float v1 = (acc[f][nf][half * 2 + 1] + bp[d + 1]) * osc;
                *(uint32_t*)(op + rowoff + d) = cvt_pair(v0, v1);
            }
        }
    }
}

// ---------------------------------------------------------------------------
// Output projection: y[8192x1024] = O_cat * wo + bo, 64x128 tiles, grid (128, 8)
// ---------------------------------------------------------------------------
__global__ __launch_bounds__(256, 2) void oproj_mma_kernel(
    const float* __restrict__ bo, float* __restrict__ y)
{
    extern __shared__ char smem[];
    const uint32_t sb = smem_to_u32(smem);
    const int tid = threadIdx.x;
    const int m0 = blockIdx.x * 64;
    const int n0 = blockIdx.y * 128;

    const char* ag = (const char*)(g_o16 + (size_t)m0 * EE);
    const char* bg = (const char*)(g_wo16 + (size_t)n0 * EE);

    float acc[2][4][4];
    gemm_core_64x128_h(sb, ag, bg, acc);

    const int warp = tid >> 5, lane = tid & 31;
    const int wm = (warp & 1) * 32, wn = (warp >> 1) * 32;
    const int r = lane >> 2, cp2 = (lane & 3) * 2;
    #pragma unroll
    for (int f = 0; f < 2; ++f) {
        #pragma unroll
        for (int half = 0; half < 2; ++half) {
            int m = m0 + wm + f * 16 + r + half * 8;
            float* row = y + (size_t)m * EE + n0 + wn;
            #pragma unroll
            for (int nf = 0; nf < 4; ++nf) {
                int col = nf * 8 + cp2;
                float2 v;
                v.x = acc[f][nf][half * 2 + 0] + bo[n0 + wn + col];
                v.y = acc[f][nf][half * 2 + 1] + bo[n0 + wn + col + 1];
                *(float2*)(row + col) = v;
            }
        }
    }
}

// ---------------------------------------------------------------------------
// Flash attention (R15-proven dynamic loop) with incremental stage base:
// compute stage and prefetch stage are identical ((ct+3)%3 == ct%3), so one
// register `base` serves both; advanced by IADD+SEL instead of IMAD chains.
// 3 KV stages + dedicated Q region, 64KB, 2 CTAs/SM, long blocks first.
// ---------------------------------------------------------------------------
#define AT_STAGE 16384
#define AT_SMEM  (4 * AT_STAGE)

__device__ __forceinline__ void attn_load_kv_at(
    uint32_t stage_base, int ct, int tid,
    const char* kg, const char* vg)
{
    const int col0 = ct * 64;
    #pragma unroll
    for (int p = 0; p < 2; ++p) {
        int idx = p * 256 + tid;
        int r = idx >> 3, c16 = (idx & 7) * 16;
        uint32_t so = SWZ128((uint32_t)(r * 128 + c16));
        size_t g = (size_t)(col0 + r) * 128 + c16;
        cp16(stage_base + so,        kg + g);
        cp16(stage_base + 8192 + so, vg + g);
    }
}

__global__ __launch_bounds__(256, 2) void attn_mma_kernel()
{
    extern __shared__ char smem[];
    const uint32_t sb = smem_to_u32(smem);
    const uint32_t qb = sb + 3 * AT_STAGE;     // dedicated Q region
    const int tid = threadIdx.x;
    const int warp = tid >> 5, lane = tid & 31;
    const int rt = (int)gridDim.x - 1 - (int)blockIdx.x;  // long blocks first
    const int bh = blockIdx.y;
    const int row0 = rt * 128;
    const int wm = warp * 16;

    const char* qg = (const char*)(g_q16 + (size_t)bh * SS * DD);
    const char* kg = (const char*)(g_k16 + (size_t)bh * SS * DD);
    const char* vg = (const char*)(g_v16 + (size_t)bh * SS * DD);

    const int nct = 2 * rt + 2;

    // ---- overlapped prologue: Q (group0) then KV stages 0..2 (groups 1..3)
    #pragma unroll
    for (int p = 0; p < 4; ++p) {
        int cc = p * 256 + tid;
        int rr = cc >> 3, c = (cc & 7) * 16;
        uint32_t so = SWZ128((uint32_t)(rr * 128 + c));
        cp16(qb + so, qg + (size_t)(row0 + rr) * 128 + c);
    }
    CP_COMMIT();                                   // g0: Q
    attn_load_kv_at(sb, 0, tid, kg, vg); CP_COMMIT();        // g1
    if (nct > 1) attn_load_kv_at(sb + AT_STAGE, 1, tid, kg, vg);
    CP_COMMIT();                                   // g2
    if (nct > 2) attn_load_kv_at(sb + 2 * AT_STAGE, 2, tid, kg, vg);
    CP_COMMIT();                                   // g3

    CP_WAIT3();            // Q complete
    __syncthreads();

    const int rbA = (lane & 7) + ((lane >> 3) & 1) * 8;
    const int cA  = (lane >> 4) & 1;
    uint32_t qf[4][4];
    #pragma unroll
    for (int c = 0; c < 4; ++c) {
        uint32_t off = SWZ128((uint32_t)((wm + rbA) * 128 + (c * 2 + cA) * 16));
        ldmx4(qf[c], qb + off);
    }

    float o[8][4];
    #pragma unroll
    for (int nf = 0; nf < 8; nf++)
        #pragma unroll
        for (int i = 0; i < 4; i++) o[nf][i] = 0.f;
    float lacc[4] = {0.f, 0.f, 0.f, 0.f};
    float mprev0 = -CUDART_INF_F, mprev1 = -CUDART_INF_F;

    const uint32_t ONE2 = 0x3C003C00u;

    const int rbB = (lane & 7) + ((lane >> 4) & 1) * 8;
    const int cB  = (lane >> 3) & 1;
    const int lr  = lane >> 2;
    const int lc2 = (lane & 3) * 2;
    const int r0g = row0 + wm + lr;

    uint32_t base = sb;    // stage ct % 3; prefetch target is the same stage

    for (int ct = 0; ct < nct; ++ct) {
        CP_WAIT2();
        __syncthreads();

        const bool active = (ct * 64) <= (row0 + wm + 15);
        if (active) {
            float s[8][4];
            #pragma unroll
            for (int nf = 0; nf < 8; nf++)
                #pragma unroll
                for (int i = 0; i < 4; i++) s[nf][i] = 0.f;

            #pragma unroll
            for (int c = 0; c < 4; ++c) {
                uint32_t kh[4][4];
                #pragma unroll
                for (int g = 0; g < 4; ++g) {
                    uint32_t off = SWZ128((uint32_t)((g * 16 + rbB) * 128 + (c * 2 + cB) * 16));
                    ldmx4(kh[g], base + off);
                }
                #pragma unroll
                for (int nf = 0; nf < 8; ++nf) {
                    int g = nf >> 1, i = (nf & 1) * 2;
                    mmah(s[nf], qf[c], kh[g][i], kh[g][i + 1]);
                }
            }

            if (ct * 64 + 63 > row0 + wm) {
                #pragma unroll
                for (int nf = 0; nf < 8; ++nf) {
                    int cg = ct * 64 + nf * 8 + lc2;
                    if (cg     > r0g)     s[nf][0] = -CUDART_INF_F;
                    if (cg + 1 > r0g)     s[nf][1] = -CUDART_INF_F;
                    if (cg     > r0g + 8) s[nf][2] = -CUDART_INF_F;
                    if (cg + 1 > r0g + 8) s[nf][3] = -CUDART_INF_F;
                }
            }

            float mt0 = -CUDART_INF_F, mt1 = -CUDART_INF_F;
            #pragma unroll
            for (int nf = 0; nf < 8; ++nf) {
                mt0 = fmaxf(mt0, fmaxf(s[nf][0], s[nf][1]));
                mt1 = fmaxf(mt1, fmaxf(s[nf][2], s[nf][3]));
            }
            mt0 = fmaxf(mt0, __shfl_xor_sync(0xffffffffu, mt0, 1));
            mt0 = fmaxf(mt0, __shfl_xor_sync(0xffffffffu, mt0, 2));
            mt1 = fmaxf(mt1, __shfl_xor_sync(0xffffffffu, mt1, 1));
            mt1 = fmaxf(mt1, __shfl_xor_sync(0xffffffffu, mt1, 2));

            float mn0 = fmaxf(mprev0, mt0);
            float mn1 = fmaxf(mprev1, mt1);
            float a0 = exp2f(mprev0 - mn0);
            float a1 = exp2f(mprev1 - mn1);
            mprev0 = mn0; mprev1 = mn1;

            lacc[0] *= a0; lacc[1] *= a0; lacc[2] *= a1; lacc[3] *= a1;
            #pragma unroll
            for (int nf = 0; nf < 8; ++nf) {
                o[nf][0] *= a0; o[nf][1] *= a0;
                o[nf][2] *= a1; o[nf][3] *= a1;
            }

            uint32_t pf[4][4];
            #pragma unroll
            for (int kk = 0; kk < 4; ++kk) {
                pf[kk][0] = h2exp2(cvtpair_f2h(s[2*kk][0]   - mn0, s[2*kk][1]   - mn0));
                pf[kk][1] = h2exp2(cvtpair_f2h(s[2*kk][2]   - mn1, s[2*kk][3]   - mn1));
                pf[kk][2] = h2exp2(cvtpair_f2h(s[2*kk+1][0] - mn0, s[2*kk+1][1] - mn0));
                pf[kk][3] = h2exp2(cvtpair_f2h(s[2*kk+1][2] - mn1, s[2*kk+1][3] - mn1));
            }

            #pragma unroll
            for (int kk = 0; kk < 4; ++kk)
                mmah(lacc, pf[kk], ONE2, ONE2);

            #pragma unroll
            for (int kk = 0; kk < 4; ++kk) {
                #pragma unroll
                for (int dd = 0; dd < 4; ++dd) {
                    uint32_t vh[4];
                    uint32_t off = SWZ128((uint32_t)((kk * 16 + rbA) * 128 + (dd * 2 + cA) * 16));
                    ldmx4t(vh, base + 8192 + off);
                    #pragma unroll
                    for (int j = 0; j < 2; ++j) {
                        int nf = dd * 2 + j;
                        mmah(o[nf], pf[kk], vh[j * 2], vh[j * 2 + 1]);
                    }
                }
            }
        }

        __syncthreads();
        if (ct + 3 < nct)
            attn_load_kv_at(base, ct + 3, tid, kg, vg);  // same stage as compute
        CP_COMMIT();

        // advance ring base: IADD + compare/select (no IMAD)
        base += AT_STAGE;
        if (base == qb) base = sb;
    }

    float inv0 = 1.f / lacc[0];
    float inv1 = 1.f / lacc[2];

    const int b = bh >> 4, h = bh & 15;
    const size_t m0G = (size_t)b * SS + (size_t)(row0 + wm + lr);
    __half* o0 = g_o16 + m0G * EE + h * DD;
    __half* o1 = o0 + (size_t)8 * EE;
    #pragma unroll
    for (int nf = 0; nf < 8; ++nf) {
        int col = nf * 8 + lc2;
        *(uint32_t*)(o0 + col) = cvt_pair(o[nf][0] * inv0, o[nf][1] * inv0);
        *(uint32_t*)(o1 + col) = cvt_pair(o[nf][2] * inv1, o[nf][3] * inv1);
    }
}

// ---------------------------------------------------------------------------
extern "C" void kernel_launch(void* const* d_in, const int* in_sizes, int n_in,
                              void* d_out, int out_size)
{
    const float* x  = (const float*)d_in[0];
    const float* wq = (const float*)d_in[1];
    const float* bq = (const float*)d_in[2];
    const float* wk = (const float*)d_in[3];
    const float* bk = (const float*)d_in[4];
    const float* wv = (const float*)d_in[5];
    const float* bv = (const float*)d_in[6];
    const float* wo = (const float*)d_in[7];
    const float* bo = (const float*)d_in[8];
    float* y = (float*)d_out;

    (void)in_sizes; (void)n_in; (void)out_size;

    cudaFuncSetAttribute(qkv_mma_kernel, cudaFuncAttributeMaxDynamicSharedMemorySize,
                         GEMM_SMEM);
    cudaFuncSetAttribute(oproj_mma_kernel, cudaFuncAttributeMaxDynamicSharedMemorySize,
                         GEMM64_SMEM);
    cudaFuncSetAttribute(attn_mma_kernel, cudaFuncAttributeMaxDynamicSharedMemorySize,
                         AT_SMEM);

    // 1) merged fp32 -> fp16 prep (x, W_all^T, wo^T)
    prep_kernel<<<5120, 256>>>(x, wq, wk, wv, wo);

    // 2) QKV projection: merged GEMM [8192 x 3072], static-stage mainloop
    qkv_mma_kernel<<<dim3(64, 24), 256, GEMM_SMEM>>>(bq, bk, bv);

    // 3) Flash attention (dynamic loop, incremental ring base)
    attn_mma_kernel<<<dim3(16, 64), 256, AT_SMEM>>>();

    // 4) Output projection: 64x128 tiles, static-stage mainloop
    oproj_mma_kernel<<<dim3(128, 8), 256, GEMM64_SMEM>>>(bo, y);
}